// round 17
// baseline (speedup 1.0000x reference)
#include <cuda_runtime.h>
#include <cstdint>

#define TT  50
#define FF  24
#define H1  64
#define LAT 32
#define H3  64
#define BMAX 8192

typedef unsigned long long u64;

__device__ float g_h1[(size_t)BMAX * TT * H1];   // [B][T][64]
__device__ float g_z [(size_t)BMAX * LAT];

__device__ __forceinline__ float sigmoidf(float v) {
    return __fdividef(1.0f, 1.0f + __expf(-v));
}
__device__ __forceinline__ u64 ffma2(u64 a, u64 b, u64 c) {
    u64 d; asm("fma.rn.f32x2 %0, %1, %2, %3;" : "=l"(d) : "l"(a), "l"(b), "l"(c)); return d;
}
__device__ __forceinline__ u64 pack2(float lo, float hi) {
    u64 r; asm("mov.b64 %0, {%1, %2};" : "=l"(r) : "f"(lo), "f"(hi)); return r;
}
__device__ __forceinline__ float2 unpack2(u64 v) {
    float2 f; asm("mov.b64 {%0, %1}, %2;" : "=f"(f.x), "=f"(f.y) : "l"(v)); return f;
}

// ---------------------------------------------------------------------------
// LSTM1 v2: x[B,T,24] -> g_h1[B,T,64]
// Weights in SMEM, accumulators in registers (2-D register tiling).
// CTA = 128 threads (4 warps), R = 32 rows (8 rows per warp), grid = B/32.
// Lane l owns z-cols 8l..8l+7 (gate-interleaved c = 4u+g -> units 2l, 2l+1)
// for its warp's 8 rows: acc[8][4] f32x2. Cell update is lane-local
// (no shuffles, no CTA barriers in the loop — warps fully independent).
// ---------------------------------------------------------------------------
#define WCK 88          // combined k: 24 (x) + 64 (h)
#define WCN 256
#define L1_SMEM_FLOATS (WCK * WCN + 4 * 8 * FF + 4 * 8 * H1)
#define L1_SMEM_BYTES  (L1_SMEM_FLOATS * 4)

__global__ void __launch_bounds__(128, 2) lstm1_kernel(
    const float* __restrict__ x, const float* __restrict__ W,
    const float* __restrict__ U, const float* __restrict__ b, int B)
{
    extern __shared__ float smem[];
    float* Wc  = smem;                      // [88][256] gate-interleaved cols
    float* xsb = smem + WCK * WCN;          // [4][8][24]
    float* hsb = xsb + 4 * 8 * FF;          // [4][8][64]

    const int tid  = threadIdx.x;
    const int w    = tid >> 5, ln = tid & 31;
    const int row0 = blockIdx.x * 32 + w * 8;

    // Load weights once. col c -> src = (c&3)*64 + (c>>2)
    for (int idx = tid; idx < WCK * WCN; idx += 128) {
        int k = idx >> 8, c = idx & 255;
        int src = (c & 3) * H1 + (c >> 2);
        Wc[idx] = (k < FF) ? W[k * 256 + src] : U[(k - FF) * 256 + src];
    }
    for (int i = tid; i < 4 * 8 * H1; i += 128) hsb[i] = 0.0f;

    // bias pairs for cols 8ln..8ln+7
    u64 bias4[4];
#pragma unroll
    for (int cp = 0; cp < 4; cp++) {
        int c0 = 8 * ln + 2 * cp, c1 = c0 + 1;
        bias4[cp] = pack2(b[(c0 & 3) * H1 + (c0 >> 2)], b[(c1 & 3) * H1 + (c1 >> 2)]);
    }
    __syncthreads();    // only CTA barrier in the kernel

    float* xsw = xsb + w * 8 * FF;   // [8][24]
    float* hsw = hsb + w * 8 * H1;   // [8][64]

    // prefetch x(0): 192 floats/warp, 6 per lane
    float xr[6];
#pragma unroll
    for (int i = 0; i < 6; i++) {
        int idx = ln + 32 * i; int r = idx / FF, k = idx - r * FF;
        int row = min(row0 + r, B - 1);
        xr[i] = x[((size_t)row * TT + 0) * FF + k];
    }

    const int u0 = 2 * ln;
    float cst[16];
#pragma unroll
    for (int i = 0; i < 16; i++) cst[i] = 0.0f;

    for (int t = 0; t < TT; t++) {
        // store x(t) to smem, prefetch x(t+1)
#pragma unroll
        for (int i = 0; i < 6; i++) {
            int idx = ln + 32 * i; int r = idx / FF, k = idx - r * FF;
            xsw[r * FF + k] = xr[i];
        }
        if (t + 1 < TT) {
#pragma unroll
            for (int i = 0; i < 6; i++) {
                int idx = ln + 32 * i; int r = idx / FF, k = idx - r * FF;
                int row = min(row0 + r, B - 1);
                xr[i] = x[((size_t)row * TT + (t + 1)) * FF + k];
            }
        }
        __syncwarp();

        u64 acc[8][4];
#pragma unroll
        for (int r = 0; r < 8; r++) {
#pragma unroll
            for (int cp = 0; cp < 4; cp++) acc[r][cp] = bias4[cp];
        }

        // x part: k = 0..23
#pragma unroll 4
        for (int k = 0; k < FF; k++) {
            const ulonglong2 wqa = *(const ulonglong2*)&Wc[k * WCN + 8 * ln];
            const ulonglong2 wqb = *(const ulonglong2*)&Wc[k * WCN + 8 * ln + 4];
#pragma unroll
            for (int r = 0; r < 8; r++) {
                const float a = xsw[r * FF + k];
                const u64 ap = pack2(a, a);
                acc[r][0] = ffma2(ap, wqa.x, acc[r][0]);
                acc[r][1] = ffma2(ap, wqa.y, acc[r][1]);
                acc[r][2] = ffma2(ap, wqb.x, acc[r][2]);
                acc[r][3] = ffma2(ap, wqb.y, acc[r][3]);
            }
        }
        // h part: k = 24..87 (u = 0..63); h(t-1)=0 at t=0 (skipped)
        if (t > 0) {
#pragma unroll 4
            for (int u = 0; u < H1; u++) {
                const ulonglong2 wqa = *(const ulonglong2*)&Wc[(FF + u) * WCN + 8 * ln];
                const ulonglong2 wqb = *(const ulonglong2*)&Wc[(FF + u) * WCN + 8 * ln + 4];
#pragma unroll
                for (int r = 0; r < 8; r++) {
                    const float a = hsw[r * H1 + u];
                    const u64 ap = pack2(a, a);
                    acc[r][0] = ffma2(ap, wqa.x, acc[r][0]);
                    acc[r][1] = ffma2(ap, wqa.y, acc[r][1]);
                    acc[r][2] = ffma2(ap, wqb.x, acc[r][2]);
                    acc[r][3] = ffma2(ap, wqb.y, acc[r][3]);
                }
            }
        }

        // lane-local gates: acc[r] = {(i,f)u0, (g,o)u0, (i,f)u1, (g,o)u1}
#pragma unroll
        for (int r = 0; r < 8; r++) {
            const float2 p0 = unpack2(acc[r][0]);
            const float2 p1 = unpack2(acc[r][1]);
            float c0v = sigmoidf(p0.y) * cst[r] + sigmoidf(p0.x) * fmaxf(p1.x, 0.0f);
            cst[r] = c0v;
            const float h0 = sigmoidf(p1.y) * fmaxf(c0v, 0.0f);
            const float2 p2 = unpack2(acc[r][2]);
            const float2 p3 = unpack2(acc[r][3]);
            float c1v = sigmoidf(p2.y) * cst[8 + r] + sigmoidf(p2.x) * fmaxf(p3.x, 0.0f);
            cst[8 + r] = c1v;
            const float h1 = sigmoidf(p3.y) * fmaxf(c1v, 0.0f);

            *(float2*)&hsw[r * H1 + u0] = make_float2(h0, h1);
            const int row = row0 + r;
            if (row < B)
                *(float2*)&g_h1[((size_t)row * TT + t) * H1 + u0] = make_float2(h0, h1);
        }
        __syncwarp();
    }
}

// ---------------------------------------------------------------------------
// LSTM2: g_h1[B,T,64] -> g_z[B,32]. 64 threads, C=2, R=8, shuffle gates,
// double-buffered hs, one barrier per step. (unchanged, R14)
// ---------------------------------------------------------------------------
__global__ void __launch_bounds__(64, 4) lstm2_kernel(
    const float* __restrict__ W, const float* __restrict__ U,
    const float* __restrict__ b, int B)
{
    constexpr int D = H1, H = LAT, G = 4 * LAT, R = 8;
    __shared__ __align__(16) float xs[2][R][D];
    __shared__ __align__(16) float hs[2][R][H];

    const int j    = threadIdx.x;
    const int uu   = j >> 1;
    const int par  = j & 1;
    const int sA   = (2 * par) * H + uu;
    const int sB   = (2 * par + 1) * H + uu;
    const int row0 = blockIdx.x * R;
    const int rlo  = 4 * par;

    u64 wA[D / 2], wB[D / 2], uA[H / 2], uB[H / 2];
#pragma unroll
    for (int k = 0; k < D / 2; k++) {
        wA[k] = pack2(W[(2 * k) * G + sA], W[(2 * k + 1) * G + sA]);
        wB[k] = pack2(W[(2 * k) * G + sB], W[(2 * k + 1) * G + sB]);
    }
#pragma unroll
    for (int k = 0; k < H / 2; k++) {
        uA[k] = pack2(U[(2 * k) * G + sA], U[(2 * k + 1) * G + sA]);
        uB[k] = pack2(U[(2 * k) * G + sB], U[(2 * k + 1) * G + sB]);
    }
    const u64 bA = pack2(b[sA], 0.0f);
    const u64 bB = pack2(b[sB], 0.0f);

    for (int idx = j; idx < R * H; idx += 64) (&hs[0][0][0])[idx] = 0.0f;

    float cst[4] = {0.0f, 0.0f, 0.0f, 0.0f};

    const int lr = j >> 3, lk = (j & 7) * 8;
    float4 xg0, xg1;
    {
        int row = min(row0 + lr, B - 1);
        const float4* p = (const float4*)&g_h1[((size_t)row * TT + 0) * D + lk];
        xg0 = p[0]; xg1 = p[1];
    }

    int buf = 0, hb = 0;
    for (int t = 0; t < TT; t++) {
        *(float4*)&xs[buf][lr][lk]     = xg0;
        *(float4*)&xs[buf][lr][lk + 4] = xg1;
        if (t + 1 < TT) {
            int row = min(row0 + lr, B - 1);
            const float4* p = (const float4*)&g_h1[((size_t)row * TT + (t + 1)) * D + lk];
            xg0 = p[0]; xg1 = p[1];
        }
        __syncthreads();

        u64 accA[R], accB[R];
#pragma unroll
        for (int r = 0; r < R; r++) { accA[r] = bA; accB[r] = bB; }
#pragma unroll
        for (int k = 0; k < D / 4; k++) {
#pragma unroll
            for (int r = 0; r < R; r++) {
                const ulonglong2 xv = *(const ulonglong2*)&xs[buf][r][4 * k];
                accA[r] = ffma2(xv.x, wA[2 * k], accA[r]);
                accA[r] = ffma2(xv.y, wA[2 * k + 1], accA[r]);
                accB[r] = ffma2(xv.x, wB[2 * k], accB[r]);
                accB[r] = ffma2(xv.y, wB[2 * k + 1], accB[r]);
            }
        }
#pragma unroll
        for (int k = 0; k < H / 4; k++) {
#pragma unroll
            for (int r = 0; r < R; r++) {
                const ulonglong2 hv = *(const ulonglong2*)&hs[hb][r][4 * k];
                accA[r] = ffma2(hv.x, uA[2 * k], accA[r]);
                accA[r] = ffma2(hv.y, uA[2 * k + 1], accA[r]);
                accB[r] = ffma2(hv.x, uB[2 * k], accB[r]);
                accB[r] = ffma2(hv.y, uB[2 * k + 1], accB[r]);
            }
        }
        float zA[R], zB[R];
#pragma unroll
        for (int r = 0; r < R; r++) {
            const float2 pA = unpack2(accA[r]);
            const float2 pB = unpack2(accB[r]);
            zA[r] = pA.x + pA.y;
            zB[r] = pB.x + pB.y;
        }
        float rA[4], rB[4];
#pragma unroll
        for (int k = 0; k < 4; k++) {
            float tA = par ? zA[k] : zA[k + 4];
            float tB = par ? zB[k] : zB[k + 4];
            rA[k] = __shfl_xor_sync(0xFFFFFFFFu, tA, 1);
            rB[k] = __shfl_xor_sync(0xFFFFFFFFu, tB, 1);
        }
#pragma unroll
        for (int k = 0; k < 4; k++) {
            const int r = rlo + k;
            const float iv = par ? rA[k] : zA[r];
            const float fv = par ? rB[k] : zB[r];
            const float gv = par ? zA[r] : rA[k];
            const float ov = par ? zB[r] : rB[k];
            cst[k] = sigmoidf(fv) * cst[k] + sigmoidf(iv) * fmaxf(gv, 0.0f);
            const float hn = sigmoidf(ov) * fmaxf(cst[k], 0.0f);
            hs[hb ^ 1][r][uu] = hn;
            if (t == TT - 1 && row0 + r < B) g_z[(size_t)(row0 + r) * H + uu] = hn;
        }
        buf ^= 1; hb ^= 1;
    }
}

// ---------------------------------------------------------------------------
// LSTM3 + Dense: g_z[B,32] -> out[B,T,24]. (unchanged, R14)
// ---------------------------------------------------------------------------
__global__ void __launch_bounds__(128, 2) lstm3_kernel(
    const float* __restrict__ W, const float* __restrict__ U,
    const float* __restrict__ b, const float* __restrict__ Wd,
    const float* __restrict__ bd, float* __restrict__ out, int B)
{
    constexpr int D = LAT, H = H3, G = 4 * H3, R = 8;
    constexpr int WDP = 68;
    __shared__ __align__(16) float zin[R][D];
    __shared__ __align__(16) float hs[2][R][H];
    __shared__ __align__(16) float wdst[FF][WDP];

    const int j    = threadIdx.x;
    const int uu   = j >> 1;
    const int par  = j & 1;
    const int sA   = (2 * par) * H + uu;
    const int sB   = (2 * par + 1) * H + uu;
    const int row0 = blockIdx.x * R;
    const int rlo  = 4 * par;

    u64 uA[H / 2], uB[H / 2];
#pragma unroll
    for (int k = 0; k < H / 2; k++) {
        uA[k] = pack2(U[(2 * k) * G + sA], U[(2 * k + 1) * G + sA]);
        uB[k] = pack2(U[(2 * k) * G + sB], U[(2 * k + 1) * G + sB]);
    }

    for (int idx = j; idx < H * FF; idx += 128) {
        int h = idx / FF, f = idx - h * FF;
        wdst[f][h] = Wd[idx];
    }
    for (int idx = j; idx < R * D; idx += 128) {
        int r = idx >> 5, k = idx & 31;
        int row = min(row0 + r, B - 1);
        zin[r][k] = g_z[(size_t)row * D + k];
    }
    for (int idx = j; idx < R * H; idx += 128) (&hs[0][0][0])[idx] = 0.0f;
    __syncthreads();

    float zwA[R], zwB[R];
    {
        const float bvA = b[sA], bvB = b[sB];
#pragma unroll
        for (int r = 0; r < R; r++) { zwA[r] = bvA; zwB[r] = bvB; }
        for (int k = 0; k < D; k++) {
            const float wkA = W[k * G + sA], wkB = W[k * G + sB];
#pragma unroll
            for (int r = 0; r < R; r++) {
                zwA[r] += zin[r][k] * wkA;
                zwB[r] += zin[r][k] * wkB;
            }
        }
    }

    float cst[4] = {0.0f, 0.0f, 0.0f, 0.0f};

    const int d0f = j % FF, d0r = j / FF;
    const int d1f = (j + 128) % FF, d1r = (j + 128) / FF;
    const float bd0 = bd[d0f];
    const float bd1 = (j < 64) ? bd[d1f] : 0.0f;

    int hb = 0;
    for (int t = 0; t < TT; t++) {
        u64 accA[R], accB[R];
#pragma unroll
        for (int r = 0; r < R; r++) {
            accA[r] = pack2(zwA[r], 0.0f);
            accB[r] = pack2(zwB[r], 0.0f);
        }
#pragma unroll
        for (int k = 0; k < H / 4; k++) {
#pragma unroll
            for (int r = 0; r < R; r++) {
                const ulonglong2 hv = *(const ulonglong2*)&hs[hb][r][4 * k];
                accA[r] = ffma2(hv.x, uA[2 * k], accA[r]);
                accA[r] = ffma2(hv.y, uA[2 * k + 1], accA[r]);
                accB[r] = ffma2(hv.x, uB[2 * k], accB[r]);
                accB[r] = ffma2(hv.y, uB[2 * k + 1], accB[r]);
            }
        }
        float zA[R], zB[R];
#pragma unroll
        for (int r = 0; r < R; r++) {
            const float2 pA = unpack2(accA[r]);
            const float2 pB = unpack2(accB[r]);
            zA[r] = pA.x + pA.y;
            zB[r] = pB.x + pB.y;
        }
        float rA[4], rB[4];
#pragma unroll
        for (int k = 0; k < 4; k++) {
            float tA = par ? zA[k] : zA[k + 4];
            float tB = par ? zB[k] : zB[k + 4];
            rA[k] = __shfl_xor_sync(0xFFFFFFFFu, tA, 1);
            rB[k] = __shfl_xor_sync(0xFFFFFFFFu, tB, 1);
        }
#pragma unroll
        for (int k = 0; k < 4; k++) {
            const int r = rlo + k;
            const float iv = par ? rA[k] : zA[r];
            const float fv = par ? rB[k] : zB[r];
            const float gv = par ? zA[r] : rA[k];
            const float ov = par ? zB[r] : rB[k];
            cst[k] = sigmoidf(fv) * cst[k] + sigmoidf(iv) * fmaxf(gv, 0.0f);
            const float hn = sigmoidf(ov) * fmaxf(cst[k], 0.0f);
            hs[hb ^ 1][r][uu] = hn;
        }
        __syncthreads();

        {
            int row = row0 + d0r;
            if (row < B) {
                u64 sacc = pack2(bd0, 0.0f);
#pragma unroll
                for (int k = 0; k < H / 4; k++) {
                    const ulonglong2 hv = *(const ulonglong2*)&hs[hb ^ 1][d0r][4 * k];
                    const ulonglong2 wv = *(const ulonglong2*)&wdst[d0f][4 * k];
                    sacc = ffma2(hv.x, wv.x, sacc);
                    sacc = ffma2(hv.y, wv.y, sacc);
                }
                const float2 p = unpack2(sacc);
                out[((size_t)row * TT + t) * FF + d0f] = p.x + p.y;
            }
        }
        if (j < 64) {
            int row = row0 + d1r;
            if (row < B) {
                u64 sacc = pack2(bd1, 0.0f);
#pragma unroll
                for (int k = 0; k < H / 4; k++) {
                    const ulonglong2 hv = *(const ulonglong2*)&hs[hb ^ 1][d1r][4 * k];
                    const ulonglong2 wv = *(const ulonglong2*)&wdst[d1f][4 * k];
                    sacc = ffma2(hv.x, wv.x, sacc);
                    sacc = ffma2(hv.y, wv.y, sacc);
                }
                const float2 p = unpack2(sacc);
                out[((size_t)row * TT + t) * FF + d1f] = p.x + p.y;
            }
        }
        hb ^= 1;
    }
}

// ---------------------------------------------------------------------------
extern "C" void kernel_launch(void* const* d_in, const int* in_sizes, int n_in,
                              void* d_out, int out_size)
{
    const float* x  = (const float*)d_in[0];
    const float* W1 = (const float*)d_in[1];
    const float* U1 = (const float*)d_in[2];
    const float* b1 = (const float*)d_in[3];
    const float* W2 = (const float*)d_in[4];
    const float* U2 = (const float*)d_in[5];
    const float* b2 = (const float*)d_in[6];
    const float* W3 = (const float*)d_in[7];
    const float* U3 = (const float*)d_in[8];
    const float* b3 = (const float*)d_in[9];
    const float* Wd = (const float*)d_in[10];
    const float* bd = (const float*)d_in[11];
    float* out = (float*)d_out;

    const int B = in_sizes[0] / (TT * FF);

    // Dynamic smem > 48KB for lstm1 weight tile. Unconditional (deterministic,
    // not an allocation); result ignored if redundant.
    cudaFuncSetAttribute(lstm1_kernel,
                         cudaFuncAttributeMaxDynamicSharedMemorySize, L1_SMEM_BYTES);

    lstm1_kernel<<<(B + 31) / 32, 128, L1_SMEM_BYTES>>>(x, W1, U1, b1, B);
    lstm2_kernel<<<(B + 7) / 8, 64>>>(W2, U2, b2, B);
    lstm3_kernel<<<(B + 7) / 8, 128>>>(W3, U3, b3, Wd, bd, out, B);
}